// round 2
// baseline (speedup 1.0000x reference)
#include <cuda_runtime.h>
#include <cuda_bf16.h>
#include <math.h>

// ---------------- problem constants ----------------
constexpr int B_  = 2;
constexpr int C_  = 64;
constexpr int H_  = 256;
constexpr int W_  = 1216;
constexpr int HW_ = H_ * W_;        // 311296
constexpr int NP  = B_ * HW_;       // 622592
constexpr int NCH = 78;             // 24 aff7 + 16 aff5 + 8 aff3 + 6*4 att + 6 mask
constexpr int ITERS = 6;

// scratch plane layout (each plane = NP floats)
constexpr int NPLANES = 90;

__device__ float g_scratch[(size_t)NPLANES * NP];
__device__ float g_wpack[NCH * 576];
__device__ float g_bpack[NCH];

__device__ __forceinline__ float sigf(float x) { return 1.0f / (1.0f + expf(-x)); }

typedef unsigned long long u64;

__device__ __forceinline__ u64 pack2(float lo, float hi) {
    u64 r;
    asm("mov.b64 %0, {%1, %2};" : "=l"(r) : "f"(lo), "f"(hi));
    return r;
}
__device__ __forceinline__ void unpack2(u64 v, float& lo, float& hi) {
    asm("mov.b64 {%0, %1}, %2;" : "=f"(lo), "=f"(hi) : "l"(v));
}
// d = a*b + d   (packed 2x fp32, exact fmaf semantics per lane)
__device__ __forceinline__ void fma2(u64& d, u64 a, u64 b) {
    asm("fma.rn.f32x2 %0, %1, %2, %0;" : "+l"(d) : "l"(a), "l"(b));
}

// ---------------- weight packing: fold scale into weights ----------------
__global__ void pack_weights(
    const float* __restrict__ w7,  const float* __restrict__ s7,  const float* __restrict__ b7,
    const float* __restrict__ w5,  const float* __restrict__ s5,  const float* __restrict__ b5,
    const float* __restrict__ w3,  const float* __restrict__ s3,  const float* __restrict__ b3,
    const float* __restrict__ wa7, const float* __restrict__ sa7, const float* __restrict__ ba7,
    const float* __restrict__ wa5, const float* __restrict__ sa5, const float* __restrict__ ba5,
    const float* __restrict__ wa3, const float* __restrict__ sa3, const float* __restrict__ ba3,
    const float* __restrict__ wa1, const float* __restrict__ sa1, const float* __restrict__ ba1,
    const float* __restrict__ wm,  const float* __restrict__ sm,  const float* __restrict__ bm)
{
    int idx = blockIdx.x * blockDim.x + threadIdx.x;
    if (idx >= NCH * 576) return;
    int ch = idx / 576;
    int e  = idx - ch * 576;
    const float *w, *s, *b; int lc;
    if      (ch < 24) { w = w7;  s = s7;  b = b7;  lc = ch;      }
    else if (ch < 40) { w = w5;  s = s5;  b = b5;  lc = ch - 24; }
    else if (ch < 48) { w = w3;  s = s3;  b = b3;  lc = ch - 40; }
    else if (ch < 54) { w = wa7; s = sa7; b = ba7; lc = ch - 48; }
    else if (ch < 60) { w = wa5; s = sa5; b = ba5; lc = ch - 54; }
    else if (ch < 66) { w = wa3; s = sa3; b = ba3; lc = ch - 60; }
    else if (ch < 72) { w = wa1; s = sa1; b = ba1; lc = ch - 66; }
    else              { w = wm;  s = sm;  b = bm;  lc = ch - 72; }
    g_wpack[idx] = w[lc * 576 + e] * s[lc];
    if (e == 0) g_bpack[ch] = b[lc];
}

// ---------------- fused 78-channel 3x3 conv (f32x2 packed FMA) ----------------
// tile: 32(x) * 16(y), 256 threads, each thread computes 2 pixels (rows tz, tz+8)
// packed lane-pair = (pixel0, pixel1); weights duplicated into both halves in smem.
//
// duplicated-weight smem layout per (ci, r): 20 floats (80B, 16B-aligned):
//   [ky*4 + kx*2]       : dup of w[ky][kx] for kx in {0,1}  (LDS.128 per ky)
//   [12 + ky*2]         : dup of w[ky][2]                   (LDS.64  per ky)
//   [18..19]            : pad
constexpr int FELEMS  = 64 * 18 * 34;          // 39168 floats
constexpr int WELEMS2 = 13 * 64 * 20;          // 16640 floats
constexpr int CONV_SMEM_BYTES = (FELEMS + WELEMS2) * 4;  // 223232

__global__ void __launch_bounds__(256, 1) conv_kernel(
    const float* __restrict__ feat, const float* __restrict__ d00)
{
    extern __shared__ float smem[];
    float* wsh = smem + FELEMS;

    const int tx = threadIdx.x & 31;
    const int tz = threadIdx.x >> 5;
    const int x0 = blockIdx.x * 32;
    const int y0 = blockIdx.y * 16;
    const int bb = blockIdx.z;

    // load feature tile with zero halo
    for (int idx = threadIdx.x; idx < FELEMS; idx += 256) {
        int ci = idx / (18 * 34);
        int r  = idx - ci * (18 * 34);
        int yy = r / 34;
        int xx = r - yy * 34;
        int gy = y0 - 1 + yy;
        int gx = x0 - 1 + xx;
        float v = 0.0f;
        if (gy >= 0 && gy < H_ && gx >= 0 && gx < W_)
            v = __ldg(&feat[((size_t)(bb * 64 + ci) * H_ + gy) * W_ + gx]);
        smem[idx] = v;
    }

    const int px  = x0 + tx;
    const int py0 = y0 + tz;
    const int p0  = bb * HW_ + py0 * W_ + px;
    const int p1  = p0 + 8 * W_;

    const float vld0 = (d00[p0] > 0.0f) ? 1.0f : 0.0f;
    const float vld1 = (d00[p1] > 0.0f) ? 1.0f : 0.0f;

    float sA7_0 = 0.f, sA5_0 = 0.f, sA3_0 = 0.f, tT7_0 = 0.f, tT5_0 = 0.f, tT3_0 = 0.f;
    float sA7_1 = 0.f, sA5_1 = 0.f, sA3_1 = 0.f, tT7_1 = 0.f, tT5_1 = 0.f, tT3_1 = 0.f;

    const float* frow = smem + tz * 34 + tx;

    #pragma unroll 1
    for (int chunk = 0; chunk < 6; ++chunk) {
        __syncthreads();
        // stage this chunk's 13x576 weights, duplicated into lane pairs
        for (int idx = threadIdx.x; idx < 13 * 576; idx += 256) {
            int r = idx / 576;
            int e = idx - r * 576;
            int ci = e / 9;
            int k  = e - ci * 9;
            int ky = k / 3, kx = k - ky * 3;
            float w = __ldg(&g_wpack[(chunk * 13 + r) * 576 + e]);
            int base = (ci * 13 + r) * 20;
            int off = (kx < 2) ? (base + ky * 4 + kx * 2) : (base + 12 + ky * 2);
            wsh[off] = w;
            wsh[off + 1] = w;
        }
        __syncthreads();

        u64 acc2[13];
        #pragma unroll
        for (int r = 0; r < 13; ++r) acc2[r] = 0ull;   // (+0.0f, +0.0f)

        #pragma unroll 1
        for (int ci = 0; ci < 64; ++ci) {
            const float* fci = frow + ci * (18 * 34);
            const float* wci = wsh + ci * (13 * 20);
            #pragma unroll
            for (int ky = 0; ky < 3; ++ky) {
                const u64 f0 = pack2(fci[ky * 34 + 0], fci[(8 + ky) * 34 + 0]);
                const u64 f1 = pack2(fci[ky * 34 + 1], fci[(8 + ky) * 34 + 1]);
                const u64 f2 = pack2(fci[ky * 34 + 2], fci[(8 + ky) * 34 + 2]);
                #pragma unroll
                for (int r = 0; r < 13; ++r) {
                    const float* wb = wci + r * 20;
                    const ulonglong2 w01 = *reinterpret_cast<const ulonglong2*>(wb + ky * 4);
                    const u64 w2 = *reinterpret_cast<const u64*>(wb + 12 + ky * 2);
                    fma2(acc2[r], w01.x, f0);
                    fma2(acc2[r], w01.y, f1);
                    fma2(acc2[r], w2,    f2);
                }
            }
        }

        // epilogue for this channel chunk
        #pragma unroll
        for (int r = 0; r < 13; ++r) {
            const int ch = chunk * 13 + r;
            const float bias = __ldg(&g_bpack[ch]);
            float v0, v1;
            unpack2(acc2[r], v0, v1);
            v0 += bias;
            v1 += bias;
            if (ch >= 48) { v0 = sigf(v0); v1 = sigf(v1); }
            if (ch >= 72) { v0 *= vld0;    v1 *= vld1;    }
            if (ch < 24)      { sA7_0 += fabsf(v0); tT7_0 += v0; sA7_1 += fabsf(v1); tT7_1 += v1; }
            else if (ch < 40) { sA5_0 += fabsf(v0); tT5_0 += v0; sA5_1 += fabsf(v1); tT5_1 += v1; }
            else if (ch < 48) { sA3_0 += fabsf(v0); tT3_0 += v0; sA3_1 += fabsf(v1); tT3_1 += v1; }
            g_scratch[(size_t)ch * NP + p0] = v0;
            g_scratch[(size_t)ch * NP + p1] = v1;
        }
    }

    g_scratch[(size_t)78 * NP + p0] = sA7_0;  g_scratch[(size_t)78 * NP + p1] = sA7_1;
    g_scratch[(size_t)79 * NP + p0] = sA5_0;  g_scratch[(size_t)79 * NP + p1] = sA5_1;
    g_scratch[(size_t)80 * NP + p0] = sA3_0;  g_scratch[(size_t)80 * NP + p1] = sA3_1;
    g_scratch[(size_t)81 * NP + p0] = tT7_0;  g_scratch[(size_t)81 * NP + p1] = tT7_1;
    g_scratch[(size_t)82 * NP + p0] = tT5_0;  g_scratch[(size_t)82 * NP + p1] = tT5_1;
    g_scratch[(size_t)83 * NP + p0] = tT3_0;  g_scratch[(size_t)83 * NP + p1] = tT3_1;
}

// ---------------- per-iteration pointwise prep ----------------
__global__ void iter_a(const float* __restrict__ dt, const float* __restrict__ d0, int it)
{
    int p = blockIdx.x * 256 + threadIdx.x;
    if (p >= NP) return;
    const float* S = g_scratch;
    float a7 = S[(size_t)(48 + it) * NP + p];
    float a5 = S[(size_t)(54 + it) * NP + p];
    float a3 = S[(size_t)(60 + it) * NP + p];
    float a1 = S[(size_t)(66 + it) * NP + p];
    float denom = fmaf(a7, S[(size_t)78 * NP + p],
                  fmaf(a5, S[(size_t)79 * NP + p],
                  fmaf(a3, S[(size_t)80 * NP + p], a1)));
    float invd = 1.0f / denom;
    float sumg = invd * fmaf(a7, S[(size_t)81 * NP + p],
                        fmaf(a5, S[(size_t)82 * NP + p],
                        fmaf(a3, S[(size_t)83 * NP + p], a1)));
    float m = invd * dt[p];
    g_scratch[(size_t)84 * NP + p] = a7 * m;
    g_scratch[(size_t)85 * NP + p] = a5 * m;
    g_scratch[(size_t)86 * NP + p] = a3 * m;
    g_scratch[(size_t)87 * NP + p] = (1.0f - sumg) * d0[p] + a1 * m;
}

// ---------------- per-iteration 48-tap gather ----------------
__device__ __constant__ const int G7DY[24] = {3,3,3,3,3,3,3, 2,2, 1,1, 0,0, -1,-1, -2,-2, -3,-3,-3,-3,-3,-3,-3};
__device__ __constant__ const int G7DX[24] = {3,2,1,0,-1,-2,-3, 3,-3, 3,-3, 3,-3, 3,-3, 3,-3, 3,2,1,0,-1,-2,-3};
__device__ __constant__ const int G5DY[16] = {2,2,2,2,2, 1,1, 0,0, -1,-1, -2,-2,-2,-2,-2};
__device__ __constant__ const int G5DX[16] = {2,1,0,-1,-2, 2,-2, 2,-2, 2,-2, 2,1,0,-1,-2};
__device__ __constant__ const int G3DY[8]  = {1,1,1, 0,0, -1,-1,-1};
__device__ __constant__ const int G3DX[8]  = {1,0,-1, 1,-1, 1,0,-1};

__global__ void iter_b(const float* __restrict__ d00, float* __restrict__ out, int it)
{
    int p = blockIdx.x * 256 + threadIdx.x;
    if (p >= NP) return;
    unsigned up = (unsigned)p;
    int b = up / (unsigned)HW_;
    unsigned r = up - (unsigned)b * HW_;
    int y = r / (unsigned)W_;
    int x = r - (unsigned)y * W_;

    const float* S = g_scratch;
    const float* A7 = S + (size_t)84 * NP;
    const float* A5 = S + (size_t)85 * NP;
    const float* A3 = S + (size_t)86 * NP;

    float acc = S[(size_t)87 * NP + p];

    #pragma unroll
    for (int t = 0; t < 24; ++t) {
        const int dy = G7DY[t], dx = G7DX[t];
        if ((unsigned)(y + dy) < (unsigned)H_ && (unsigned)(x + dx) < (unsigned)W_) {
            int q = p + dy * W_ + dx;
            acc = fmaf(S[(size_t)t * NP + q], A7[q], acc);
        }
    }
    #pragma unroll
    for (int t = 0; t < 16; ++t) {
        const int dy = G5DY[t], dx = G5DX[t];
        if ((unsigned)(y + dy) < (unsigned)H_ && (unsigned)(x + dx) < (unsigned)W_) {
            int q = p + dy * W_ + dx;
            acc = fmaf(S[(size_t)(24 + t) * NP + q], A5[q], acc);
        }
    }
    #pragma unroll
    for (int t = 0; t < 8; ++t) {
        const int dy = G3DY[t], dx = G3DX[t];
        if ((unsigned)(y + dy) < (unsigned)H_ && (unsigned)(x + dx) < (unsigned)W_) {
            int q = p + dy * W_ + dx;
            acc = fmaf(S[(size_t)(40 + t) * NP + q], A3[q], acc);
        }
    }

    float mask = S[(size_t)(72 + it) * NP + p];
    out[p] = mask * d00[p] + (1.0f - mask) * acc;
}

// ---------------- launch ----------------
extern "C" void kernel_launch(void* const* d_in, const int* in_sizes, int n_in,
                              void* d_out, int out_size)
{
    const float* feat = (const float*)d_in[0];
    const float* d0   = (const float*)d_in[1];
    const float* d00  = (const float*)d_in[2];

    cudaFuncSetAttribute(conv_kernel, cudaFuncAttributeMaxDynamicSharedMemorySize,
                         CONV_SMEM_BYTES);

    pack_weights<<<(NCH * 576 + 255) / 256, 256>>>(
        (const float*)d_in[3],  (const float*)d_in[4],  (const float*)d_in[5],
        (const float*)d_in[6],  (const float*)d_in[7],  (const float*)d_in[8],
        (const float*)d_in[9],  (const float*)d_in[10], (const float*)d_in[11],
        (const float*)d_in[12], (const float*)d_in[13], (const float*)d_in[14],
        (const float*)d_in[15], (const float*)d_in[16], (const float*)d_in[17],
        (const float*)d_in[18], (const float*)d_in[19], (const float*)d_in[20],
        (const float*)d_in[21], (const float*)d_in[22], (const float*)d_in[23],
        (const float*)d_in[24], (const float*)d_in[25], (const float*)d_in[26]);

    conv_kernel<<<dim3(W_ / 32, H_ / 16, B_), 256, CONV_SMEM_BYTES>>>(feat, d00);

    void* sptr = nullptr;
    cudaGetSymbolAddress(&sptr, g_scratch);
    float* S = (float*)sptr;

    const int nblk = NP / 256;  // 2432 exact
    for (int it = 0; it < ITERS; ++it) {
        const float* dtcur = (it == 0) ? d0 : S + (size_t)(88 + ((it - 1) & 1)) * NP;
        float* dtnext = (it == ITERS - 1) ? (float*)d_out
                                          : S + (size_t)(88 + (it & 1)) * NP;
        iter_a<<<nblk, 256>>>(dtcur, d0, it);
        iter_b<<<nblk, 256>>>(d00, dtnext, it);
    }
}

// round 3
// speedup vs baseline: 3.7586x; 3.7586x over previous
#include <cuda_runtime.h>
#include <cuda_fp16.h>
#include <math.h>

// ---------------- problem constants ----------------
constexpr int B_  = 2;
constexpr int C_  = 64;
constexpr int H_  = 256;
constexpr int W_  = 1216;
constexpr int HW_ = H_ * W_;        // 311296
constexpr int NP  = B_ * HW_;       // 622592
constexpr int NCH = 78;
constexpr int ITERS = 6;
constexpr int NPLANES = 90;

__device__ float g_scratch[(size_t)NPLANES * NP];
__device__ float g_wpack[NCH * 576];
__device__ float g_bpack[NCH];
// fragment-preordered fp16 weights: [36 ksteps][10 nfrags][32 lanes] x uint2
__device__ uint2 g_wfrag[36 * 10 * 32];

__device__ __forceinline__ float sigf(float x) { return 1.0f / (1.0f + expf(-x)); }

// ---------------- weight packing: fold scale into weights ----------------
__global__ void pack_weights(
    const float* __restrict__ w7,  const float* __restrict__ s7,  const float* __restrict__ b7,
    const float* __restrict__ w5,  const float* __restrict__ s5,  const float* __restrict__ b5,
    const float* __restrict__ w3,  const float* __restrict__ s3,  const float* __restrict__ b3,
    const float* __restrict__ wa7, const float* __restrict__ sa7, const float* __restrict__ ba7,
    const float* __restrict__ wa5, const float* __restrict__ sa5, const float* __restrict__ ba5,
    const float* __restrict__ wa3, const float* __restrict__ sa3, const float* __restrict__ ba3,
    const float* __restrict__ wa1, const float* __restrict__ sa1, const float* __restrict__ ba1,
    const float* __restrict__ wm,  const float* __restrict__ sm,  const float* __restrict__ bm)
{
    int idx = blockIdx.x * blockDim.x + threadIdx.x;
    if (idx >= NCH * 576) return;
    int ch = idx / 576;
    int e  = idx - ch * 576;
    const float *w, *s, *b; int lc;
    if      (ch < 24) { w = w7;  s = s7;  b = b7;  lc = ch;      }
    else if (ch < 40) { w = w5;  s = s5;  b = b5;  lc = ch - 24; }
    else if (ch < 48) { w = w3;  s = s3;  b = b3;  lc = ch - 40; }
    else if (ch < 54) { w = wa7; s = sa7; b = ba7; lc = ch - 48; }
    else if (ch < 60) { w = wa5; s = sa5; b = ba5; lc = ch - 54; }
    else if (ch < 66) { w = wa3; s = sa3; b = ba3; lc = ch - 60; }
    else if (ch < 72) { w = wa1; s = sa1; b = ba1; lc = ch - 66; }
    else              { w = wm;  s = sm;  b = bm;  lc = ch - 72; }
    g_wpack[idx] = w[lc * 576 + e] * s[lc];
    if (e == 0) g_bpack[ch] = b[lc];
}

// ---------------- pre-linearize weights into mma b-fragment order ----------------
// k-order: k = tap*64 + ci ; kstep s = tap*4 + kc covers ci in [kc*16, kc*16+16)
// b frag (n8k16, col-major B): reg0 <-> k = 2*(lane&3)+{0,1}, n = lane>>2
//                              reg1 <-> k = 2*(lane&3)+8+{0,1}
__global__ void pack_frags()
{
    int idx = blockIdx.x * 256 + threadIdx.x;
    if (idx >= 36 * 10 * 32) return;
    int lane = idx & 31;
    int nf   = (idx >> 5) % 10;
    int s    = idx / 320;          // 0..35
    int tap  = s >> 2;             // 0..8
    int kc   = s & 3;
    int n    = nf * 8 + (lane >> 2);
    int t4   = lane & 3;
    unsigned regs[2];
    #pragma unroll
    for (int r8 = 0; r8 < 2; ++r8) {
        int kl  = t4 * 2 + r8 * 8;
        int ci0 = kc * 16 + kl;
        float v0 = 0.f, v1 = 0.f;
        if (n < NCH) {
            v0 = g_wpack[n * 576 + ci0 * 9 + tap];
            v1 = g_wpack[n * 576 + (ci0 + 1) * 9 + tap];
        }
        unsigned lo = __half_as_ushort(__float2half(v0));
        unsigned hi = __half_as_ushort(__float2half(v1));
        regs[r8] = (hi << 16) | lo;
    }
    g_wfrag[idx] = make_uint2(regs[0], regs[1]);
}

// ---------------- tensor-core conv ----------------
// CTA tile: 4 y-rows x 128 x  (M=512), N=80 (78 + 2 pad), K=576
// 512 threads = 16 warps; warp w: row = w>>2, x-quarter = (w&3)*32; warp tile m32 x n80
constexpr int F_HALFS = 64 * 6 * 132;                 // 50688 halfs
constexpr int F_BYTES = F_HALFS * 2;                  // 101376
constexpr int WF_U2   = 36 * 10 * 32;                 // 11520 uint2
constexpr int CONV_SMEM = F_BYTES + WF_U2 * 8;        // 193536

__device__ __forceinline__ void mma16816(float* d, const unsigned* a, uint2 b)
{
    asm volatile(
        "mma.sync.aligned.m16n8k16.row.col.f32.f16.f16.f32 "
        "{%0,%1,%2,%3}, {%4,%5,%6,%7}, {%8,%9}, {%0,%1,%2,%3};"
        : "+f"(d[0]), "+f"(d[1]), "+f"(d[2]), "+f"(d[3])
        : "r"(a[0]), "r"(a[1]), "r"(a[2]), "r"(a[3]), "r"(b.x), "r"(b.y));
}

__global__ void __launch_bounds__(512, 1) conv_kernel(
    const float* __restrict__ feat, const float* __restrict__ d00)
{
    extern __shared__ char smem[];
    half*  F   = (half*)smem;
    uint2* wsh = (uint2*)(smem + F_BYTES);

    const int tid = threadIdx.x;
    const int bx  = blockIdx.x;
    const int x0  = (bx < 9) ? bx * 128 : (W_ - 128);   // last tile overlaps
    const int y0  = blockIdx.y * 4;
    const int bb  = blockIdx.z;

    // load feature tile -> fp16 SMEM [64ci][6 rows][132 x] (130 valid cols)
    for (int idx = tid; idx < 64 * 6 * 130; idx += 512) {
        int ci  = idx / (6 * 130);
        int rem = idx - ci * (6 * 130);
        int yy  = rem / 130;
        int xx  = rem - yy * 130;
        int gy  = y0 - 1 + yy;
        int gx  = x0 - 1 + xx;
        float v = 0.0f;
        if ((unsigned)gy < (unsigned)H_ && (unsigned)gx < (unsigned)W_)
            v = __ldg(&feat[((size_t)(bb * 64 + ci) * H_ + gy) * W_ + gx]);
        F[(ci * 6 + yy) * 132 + xx] = __float2half(v);
    }
    // load pre-ordered weight fragments
    for (int idx = tid; idx < WF_U2; idx += 512)
        wsh[idx] = __ldg(&g_wfrag[idx]);
    __syncthreads();

    const int w     = tid >> 5;
    const int lane  = tid & 31;
    const int rowl  = w >> 2;               // 0..3
    const int xwarp = (w & 3) * 32;         // 0,32,64,96
    const int q     = lane >> 2;            // 0..7
    const int t4    = lane & 3;             // 0..3

    float C[2][10][4];
    #pragma unroll
    for (int mf = 0; mf < 2; ++mf)
        #pragma unroll
        for (int nf = 0; nf < 10; ++nf)
            #pragma unroll
            for (int j = 0; j < 4; ++j) C[mf][nf][j] = 0.0f;

    #pragma unroll 1
    for (int tap = 0; tap < 9; ++tap) {
        const int ky = tap / 3;
        const int kx = tap - ky * 3;
        // F base for this tap at this thread's (row, x) origin:
        const int xbase = xwarp + q + kx;           // + mf*16 + r8*8
        const int ybase = rowl + ky;

        #pragma unroll
        for (int kc = 0; kc < 4; ++kc) {
            // ---- A fragments (2 m16 frags) ----
            unsigned a[2][4];
            #pragma unroll
            for (int mf = 0; mf < 2; ++mf) {
                #pragma unroll
                for (int cc8 = 0; cc8 < 2; ++cc8) {
                    const int ci = kc * 16 + t4 * 2 + cc8 * 8;
                    const half* fp = F + ((size_t)ci * 6 + ybase) * 132 + xbase + mf * 16;
                    #pragma unroll
                    for (int r8 = 0; r8 < 2; ++r8) {
                        half h0 = fp[r8 * 8];             // ci
                        half h1 = fp[r8 * 8 + 6 * 132];   // ci+1
                        unsigned lo = __half_as_ushort(h0);
                        unsigned hi = __half_as_ushort(h1);
                        a[mf][cc8 * 2 + r8] = (hi << 16) | lo;
                    }
                }
            }
            // ---- B fragments + MMA ----
            const int s = tap * 4 + kc;
            const uint2* brow = wsh + (size_t)s * 320 + lane;
            #pragma unroll
            for (int nf = 0; nf < 10; ++nf) {
                uint2 b = brow[nf * 32];
                mma16816(C[0][nf], a[0], b);
                mma16816(C[1][nf], a[1], b);
            }
        }
    }

    // ---- epilogue: bias, activations, group reductions, stores ----
    #pragma unroll
    for (int mf = 0; mf < 2; ++mf) {
        #pragma unroll
        for (int r8 = 0; r8 < 2; ++r8) {
            const int x = x0 + xwarp + mf * 16 + q + r8 * 8;
            const int y = y0 + rowl;
            const int p = bb * HW_ + y * W_ + x;
            const float vld = (d00[p] > 0.0f) ? 1.0f : 0.0f;

            float s7 = 0.f, t7 = 0.f, s5 = 0.f, t5 = 0.f, s3 = 0.f, t3 = 0.f;
            #pragma unroll
            for (int nf = 0; nf < 10; ++nf) {
                #pragma unroll
                for (int j = 0; j < 2; ++j) {
                    const int ch = nf * 8 + t4 * 2 + j;
                    if (ch >= NCH) continue;   // compile-time prunable only partially; fine
                    float v = C[mf][nf][r8 * 2 + j] + __ldg(&g_bpack[ch]);
                    if (ch >= 48) v = sigf(v);
                    if (ch >= 72) v *= vld;
                    if (ch < 24)      { s7 += fabsf(v); t7 += v; }
                    else if (ch < 40) { s5 += fabsf(v); t5 += v; }
                    else if (ch < 48) { s3 += fabsf(v); t3 += v; }
                    g_scratch[(size_t)ch * NP + p] = v;
                }
            }
            // combine over the 4 lanes sharing this pixel (lane>>2 equal)
            #pragma unroll
            for (int d = 1; d <= 2; d <<= 1) {
                s7 += __shfl_xor_sync(0xffffffffu, s7, d);
                t7 += __shfl_xor_sync(0xffffffffu, t7, d);
                s5 += __shfl_xor_sync(0xffffffffu, s5, d);
                t5 += __shfl_xor_sync(0xffffffffu, t5, d);
                s3 += __shfl_xor_sync(0xffffffffu, s3, d);
                t3 += __shfl_xor_sync(0xffffffffu, t3, d);
            }
            if (t4 == 0) {
                g_scratch[(size_t)78 * NP + p] = s7;
                g_scratch[(size_t)79 * NP + p] = s5;
                g_scratch[(size_t)80 * NP + p] = s3;
                g_scratch[(size_t)81 * NP + p] = t7;
                g_scratch[(size_t)82 * NP + p] = t5;
                g_scratch[(size_t)83 * NP + p] = t3;
            }
        }
    }
}

// ---------------- per-iteration pointwise prep ----------------
__global__ void iter_a(const float* __restrict__ dt, const float* __restrict__ d0, int it)
{
    int p = blockIdx.x * 256 + threadIdx.x;
    if (p >= NP) return;
    const float* S = g_scratch;
    float a7 = S[(size_t)(48 + it) * NP + p];
    float a5 = S[(size_t)(54 + it) * NP + p];
    float a3 = S[(size_t)(60 + it) * NP + p];
    float a1 = S[(size_t)(66 + it) * NP + p];
    float denom = fmaf(a7, S[(size_t)78 * NP + p],
                  fmaf(a5, S[(size_t)79 * NP + p],
                  fmaf(a3, S[(size_t)80 * NP + p], a1)));
    float invd = 1.0f / denom;
    float sumg = invd * fmaf(a7, S[(size_t)81 * NP + p],
                        fmaf(a5, S[(size_t)82 * NP + p],
                        fmaf(a3, S[(size_t)83 * NP + p], a1)));
    float m = invd * dt[p];
    g_scratch[(size_t)84 * NP + p] = a7 * m;
    g_scratch[(size_t)85 * NP + p] = a5 * m;
    g_scratch[(size_t)86 * NP + p] = a3 * m;
    g_scratch[(size_t)87 * NP + p] = (1.0f - sumg) * d0[p] + a1 * m;
}

// ---------------- per-iteration 48-tap gather ----------------
__device__ __constant__ const int G7DY[24] = {3,3,3,3,3,3,3, 2,2, 1,1, 0,0, -1,-1, -2,-2, -3,-3,-3,-3,-3,-3,-3};
__device__ __constant__ const int G7DX[24] = {3,2,1,0,-1,-2,-3, 3,-3, 3,-3, 3,-3, 3,-3, 3,-3, 3,2,1,0,-1,-2,-3};
__device__ __constant__ const int G5DY[16] = {2,2,2,2,2, 1,1, 0,0, -1,-1, -2,-2,-2,-2,-2};
__device__ __constant__ const int G5DX[16] = {2,1,0,-1,-2, 2,-2, 2,-2, 2,-2, 2,1,0,-1,-2};
__device__ __constant__ const int G3DY[8]  = {1,1,1, 0,0, -1,-1,-1};
__device__ __constant__ const int G3DX[8]  = {1,0,-1, 1,-1, 1,0,-1};

__global__ void iter_b(const float* __restrict__ d00, float* __restrict__ out, int it)
{
    int p = blockIdx.x * 256 + threadIdx.x;
    if (p >= NP) return;
    unsigned up = (unsigned)p;
    int b = up / (unsigned)HW_;
    unsigned r = up - (unsigned)b * HW_;
    int y = r / (unsigned)W_;
    int x = r - (unsigned)y * W_;

    const float* S = g_scratch;
    const float* A7 = S + (size_t)84 * NP;
    const float* A5 = S + (size_t)85 * NP;
    const float* A3 = S + (size_t)86 * NP;

    float acc = S[(size_t)87 * NP + p];

    #pragma unroll
    for (int t = 0; t < 24; ++t) {
        const int dy = G7DY[t], dx = G7DX[t];
        if ((unsigned)(y + dy) < (unsigned)H_ && (unsigned)(x + dx) < (unsigned)W_) {
            int q = p + dy * W_ + dx;
            acc = fmaf(S[(size_t)t * NP + q], A7[q], acc);
        }
    }
    #pragma unroll
    for (int t = 0; t < 16; ++t) {
        const int dy = G5DY[t], dx = G5DX[t];
        if ((unsigned)(y + dy) < (unsigned)H_ && (unsigned)(x + dx) < (unsigned)W_) {
            int q = p + dy * W_ + dx;
            acc = fmaf(S[(size_t)(24 + t) * NP + q], A5[q], acc);
        }
    }
    #pragma unroll
    for (int t = 0; t < 8; ++t) {
        const int dy = G3DY[t], dx = G3DX[t];
        if ((unsigned)(y + dy) < (unsigned)H_ && (unsigned)(x + dx) < (unsigned)W_) {
            int q = p + dy * W_ + dx;
            acc = fmaf(S[(size_t)(40 + t) * NP + q], A3[q], acc);
        }
    }

    float mask = S[(size_t)(72 + it) * NP + p];
    out[p] = mask * d00[p] + (1.0f - mask) * acc;
}

// ---------------- launch ----------------
extern "C" void kernel_launch(void* const* d_in, const int* in_sizes, int n_in,
                              void* d_out, int out_size)
{
    const float* feat = (const float*)d_in[0];
    const float* d0   = (const float*)d_in[1];
    const float* d00  = (const float*)d_in[2];

    cudaFuncSetAttribute(conv_kernel, cudaFuncAttributeMaxDynamicSharedMemorySize,
                         CONV_SMEM);

    pack_weights<<<(NCH * 576 + 255) / 256, 256>>>(
        (const float*)d_in[3],  (const float*)d_in[4],  (const float*)d_in[5],
        (const float*)d_in[6],  (const float*)d_in[7],  (const float*)d_in[8],
        (const float*)d_in[9],  (const float*)d_in[10], (const float*)d_in[11],
        (const float*)d_in[12], (const float*)d_in[13], (const float*)d_in[14],
        (const float*)d_in[15], (const float*)d_in[16], (const float*)d_in[17],
        (const float*)d_in[18], (const float*)d_in[19], (const float*)d_in[20],
        (const float*)d_in[21], (const float*)d_in[22], (const float*)d_in[23],
        (const float*)d_in[24], (const float*)d_in[25], (const float*)d_in[26]);

    pack_frags<<<(36 * 10 * 32 + 255) / 256, 256>>>();

    conv_kernel<<<dim3(10, H_ / 4, B_), 512, CONV_SMEM>>>(feat, d00);

    void* sptr = nullptr;
    cudaGetSymbolAddress(&sptr, g_scratch);
    float* S = (float*)sptr;

    const int nblk = NP / 256;  // 2432 exact
    for (int it = 0; it < ITERS; ++it) {
        const float* dtcur = (it == 0) ? d0 : S + (size_t)(88 + ((it - 1) & 1)) * NP;
        float* dtnext = (it == ITERS - 1) ? (float*)d_out
                                          : S + (size_t)(88 + (it & 1)) * NP;
        iter_a<<<nblk, 256>>>(dtcur, d0, it);
        iter_b<<<nblk, 256>>>(d00, dtnext, it);
    }
}

// round 4
// speedup vs baseline: 4.0539x; 1.0786x over previous
#include <cuda_runtime.h>
#include <cuda_fp16.h>
#include <math.h>

// ---------------- problem constants ----------------
constexpr int B_  = 2;
constexpr int C_  = 64;
constexpr int H_  = 256;
constexpr int W_  = 1216;
constexpr int HW_ = H_ * W_;        // 311296
constexpr int NP  = B_ * HW_;       // 622592
constexpr int NCH = 78;
constexpr int ITERS = 6;

// fp32 scratch planes (post-conv, non-aff):
// 0-5 att7, 6-11 att5, 12-17 att3, 18-23 att1, 24-29 mask,
// 30 SA7, 31 SA5, 32 SA3, 33 T7, 34 T5, 35 T3,
// 36 A7, 37 A5, 38 A3, 39 BASE, 40/41 dt ping-pong
constexpr int NPLANES = 42;

__device__ float  g_scratch[(size_t)NPLANES * NP];
__device__ __half g_aff[(size_t)48 * NP];            // fp16 aff planes (0-23:7, 24-39:5, 40-47:3)
__device__ float  g_wpack[NCH * 576];
__device__ float  g_bpack[NCH];
__device__ uint2  g_wfrag[36 * 10 * 32];

__device__ __forceinline__ float sigf(float x) { return 1.0f / (1.0f + expf(-x)); }

// ---------------- weight packing ----------------
__global__ void pack_weights(
    const float* __restrict__ w7,  const float* __restrict__ s7,  const float* __restrict__ b7,
    const float* __restrict__ w5,  const float* __restrict__ s5,  const float* __restrict__ b5,
    const float* __restrict__ w3,  const float* __restrict__ s3,  const float* __restrict__ b3,
    const float* __restrict__ wa7, const float* __restrict__ sa7, const float* __restrict__ ba7,
    const float* __restrict__ wa5, const float* __restrict__ sa5, const float* __restrict__ ba5,
    const float* __restrict__ wa3, const float* __restrict__ sa3, const float* __restrict__ ba3,
    const float* __restrict__ wa1, const float* __restrict__ sa1, const float* __restrict__ ba1,
    const float* __restrict__ wm,  const float* __restrict__ sm,  const float* __restrict__ bm)
{
    int idx = blockIdx.x * blockDim.x + threadIdx.x;
    if (idx >= NCH * 576) return;
    int ch = idx / 576;
    int e  = idx - ch * 576;
    const float *w, *s, *b; int lc;
    if      (ch < 24) { w = w7;  s = s7;  b = b7;  lc = ch;      }
    else if (ch < 40) { w = w5;  s = s5;  b = b5;  lc = ch - 24; }
    else if (ch < 48) { w = w3;  s = s3;  b = b3;  lc = ch - 40; }
    else if (ch < 54) { w = wa7; s = sa7; b = ba7; lc = ch - 48; }
    else if (ch < 60) { w = wa5; s = sa5; b = ba5; lc = ch - 54; }
    else if (ch < 66) { w = wa3; s = sa3; b = ba3; lc = ch - 60; }
    else if (ch < 72) { w = wa1; s = sa1; b = ba1; lc = ch - 66; }
    else              { w = wm;  s = sm;  b = bm;  lc = ch - 72; }
    g_wpack[idx] = w[lc * 576 + e] * s[lc];
    if (e == 0) g_bpack[ch] = b[lc];
}

// ---------------- pre-linearize weights into mma b-fragment order ----------------
__global__ void pack_frags()
{
    int idx = blockIdx.x * 256 + threadIdx.x;
    if (idx >= 36 * 10 * 32) return;
    int lane = idx & 31;
    int nf   = (idx >> 5) % 10;
    int s    = idx / 320;
    int tap  = s >> 2;
    int kc   = s & 3;
    int n    = nf * 8 + (lane >> 2);
    int t4   = lane & 3;
    unsigned regs[2];
    #pragma unroll
    for (int r8 = 0; r8 < 2; ++r8) {
        int ci0 = kc * 16 + t4 * 2 + r8 * 8;
        float v0 = 0.f, v1 = 0.f;
        if (n < NCH) {
            v0 = g_wpack[n * 576 + ci0 * 9 + tap];
            v1 = g_wpack[n * 576 + (ci0 + 1) * 9 + tap];
        }
        unsigned lo = __half_as_ushort(__float2half(v0));
        unsigned hi = __half_as_ushort(__float2half(v1));
        regs[r8] = (hi << 16) | lo;
    }
    g_wfrag[idx] = make_uint2(regs[0], regs[1]);
}

// ---------------- tensor-core conv (channel-last + ldmatrix) ----------------
// CTA tile: 4 y-rows x 128 x (M=512), N=80 pad, K=576. 512 thr = 16 warps.
// F smem layout (fp16, channel-last, 16B-unit xor swizzle):
//   half index = ((yy*132)+xx)*64 + (( (ci>>3) ^ (xx&7) )*8) + (ci&7)
constexpr int F_BYTES = 6 * 132 * 64 * 2;             // 101376
constexpr int WF_U2   = 36 * 10 * 32;                 // 11520 uint2
constexpr int CONV_SMEM = F_BYTES + WF_U2 * 8;        // 193536

__device__ __forceinline__ void mma16816(float* d, const unsigned* a, uint2 b)
{
    asm volatile(
        "mma.sync.aligned.m16n8k16.row.col.f32.f16.f16.f32 "
        "{%0,%1,%2,%3}, {%4,%5,%6,%7}, {%8,%9}, {%0,%1,%2,%3};"
        : "+f"(d[0]), "+f"(d[1]), "+f"(d[2]), "+f"(d[3])
        : "r"(a[0]), "r"(a[1]), "r"(a[2]), "r"(a[3]), "r"(b.x), "r"(b.y));
}

__device__ __forceinline__ void ldsm_x4(unsigned* a, unsigned addr)
{
    asm volatile(
        "ldmatrix.sync.aligned.m8n8.x4.shared.b16 {%0,%1,%2,%3}, [%4];"
        : "=r"(a[0]), "=r"(a[1]), "=r"(a[2]), "=r"(a[3]) : "r"(addr));
}

__global__ void __launch_bounds__(512, 1) conv_kernel(
    const float* __restrict__ feat, const float* __restrict__ d00)
{
    extern __shared__ char smem[];
    half*  F   = (half*)smem;
    uint2* wsh = (uint2*)(smem + F_BYTES);

    const int tid = threadIdx.x;
    const int bx  = blockIdx.x;
    const int x0  = (bx < 9) ? bx * 128 : (W_ - 128);
    const int y0  = blockIdx.y * 4;
    const int bb  = blockIdx.z;

    // feature tile load: coalesced over xx, transposed to channel-last fp16
    for (int idx = tid; idx < 6 * 130 * 32; idx += 512) {
        int xx  = idx % 130;
        int rem = idx / 130;
        int t2  = rem & 31;
        int yy  = rem >> 5;
        int c   = t2 * 2;
        int gy  = y0 - 1 + yy;
        int gx  = x0 - 1 + xx;
        float v0 = 0.f, v1 = 0.f;
        if ((unsigned)gy < (unsigned)H_ && (unsigned)gx < (unsigned)W_) {
            size_t base = ((size_t)(bb * 64 + c) * H_ + gy) * W_ + gx;
            v0 = __ldg(&feat[base]);
            v1 = __ldg(&feat[base + (size_t)HW_]);
        }
        unsigned lo = __half_as_ushort(__float2half(v0));
        unsigned hi = __half_as_ushort(__float2half(v1));
        int u = (c >> 3) ^ (xx & 7);
        int hidx = (yy * 132 + xx) * 64 + u * 8 + (c & 7);
        *reinterpret_cast<unsigned*>((char*)F + hidx * 2) = (hi << 16) | lo;
    }
    for (int idx = tid; idx < WF_U2; idx += 512)
        wsh[idx] = __ldg(&g_wfrag[idx]);
    __syncthreads();

    const int w     = tid >> 5;
    const int lane  = tid & 31;
    const int rowl  = w >> 2;
    const int xwarp = (w & 3) * 32;
    const int q     = lane >> 2;
    const int t4    = lane & 3;
    const int jrow  = ((lane >> 3) & 1) * 8 + (lane & 7);  // pixel-row offset for ldmatrix
    const int jhalf = lane >> 4;                           // k-unit offset (0/1)

    unsigned Fb;
    {
        unsigned long long gp = (unsigned long long)__cvta_generic_to_shared(F);
        Fb = (unsigned)gp;
    }

    float C[2][10][4];
    #pragma unroll
    for (int mf = 0; mf < 2; ++mf)
        #pragma unroll
        for (int nf = 0; nf < 10; ++nf)
            #pragma unroll
            for (int j = 0; j < 4; ++j) C[mf][nf][j] = 0.0f;

    #pragma unroll 1
    for (int tap = 0; tap < 9; ++tap) {
        const int ky = tap / 3;
        const int kx = tap - ky * 3;
        unsigned pb[2]; int xk[2];
        #pragma unroll
        for (int mf = 0; mf < 2; ++mf) {
            int xx = xwarp + mf * 16 + jrow + kx;
            xk[mf] = (xx & 7) << 4;
            pb[mf] = Fb + (((rowl + ky) * 132 + xx) << 7);
        }
        #pragma unroll
        for (int kc = 0; kc < 4; ++kc) {
            unsigned a0[4], a1[4];
            const int ubase = (kc * 2 + jhalf) << 4;
            ldsm_x4(a0, pb[0] + (ubase ^ xk[0]));
            ldsm_x4(a1, pb[1] + (ubase ^ xk[1]));
            const uint2* brow = wsh + (size_t)(tap * 4 + kc) * 320 + lane;
            #pragma unroll
            for (int nf = 0; nf < 10; ++nf) {
                uint2 b = brow[nf * 32];
                mma16816(C[0][nf], a0, b);
                mma16816(C[1][nf], a1, b);
            }
        }
    }

    // ---- epilogue ----
    #pragma unroll
    for (int mf = 0; mf < 2; ++mf) {
        #pragma unroll
        for (int r8 = 0; r8 < 2; ++r8) {
            const int x = x0 + xwarp + mf * 16 + q + r8 * 8;
            const int y = y0 + rowl;
            const int p = bb * HW_ + y * W_ + x;
            const float vld = (d00[p] > 0.0f) ? 1.0f : 0.0f;

            float s7 = 0.f, t7 = 0.f, s5 = 0.f, t5 = 0.f, s3 = 0.f, t3 = 0.f;
            #pragma unroll
            for (int nf = 0; nf < 10; ++nf) {
                #pragma unroll
                for (int j = 0; j < 2; ++j) {
                    const int ch = nf * 8 + t4 * 2 + j;
                    if (ch >= NCH) continue;
                    float v = C[mf][nf][r8 * 2 + j] + __ldg(&g_bpack[ch]);
                    if (ch < 48) {
                        // round to fp16 FIRST so normalization sums match stored values
                        half hv = __float2half(v);
                        float vr = __half2float(hv);
                        if (ch < 24)      { s7 += fabsf(vr); t7 += vr; }
                        else if (ch < 40) { s5 += fabsf(vr); t5 += vr; }
                        else              { s3 += fabsf(vr); t3 += vr; }
                        g_aff[(size_t)ch * NP + p] = hv;
                    } else {
                        v = sigf(v);
                        if (ch >= 72) v *= vld;
                        g_scratch[(size_t)(ch - 48) * NP + p] = v;
                    }
                }
            }
            #pragma unroll
            for (int d = 1; d <= 2; d <<= 1) {
                s7 += __shfl_xor_sync(0xffffffffu, s7, d);
                t7 += __shfl_xor_sync(0xffffffffu, t7, d);
                s5 += __shfl_xor_sync(0xffffffffu, s5, d);
                t5 += __shfl_xor_sync(0xffffffffu, t5, d);
                s3 += __shfl_xor_sync(0xffffffffu, s3, d);
                t3 += __shfl_xor_sync(0xffffffffu, t3, d);
            }
            if (t4 == 0) {
                g_scratch[(size_t)30 * NP + p] = s7;
                g_scratch[(size_t)31 * NP + p] = s5;
                g_scratch[(size_t)32 * NP + p] = s3;
                g_scratch[(size_t)33 * NP + p] = t7;
                g_scratch[(size_t)34 * NP + p] = t5;
                g_scratch[(size_t)35 * NP + p] = t3;
            }
        }
    }
}

// ---------------- per-iteration pointwise prep ----------------
__global__ void iter_a(const float* __restrict__ dt, const float* __restrict__ d0, int it)
{
    int p = blockIdx.x * 256 + threadIdx.x;
    if (p >= NP) return;
    const float* S = g_scratch;
    float a7 = S[(size_t)(0  + it) * NP + p];
    float a5 = S[(size_t)(6  + it) * NP + p];
    float a3 = S[(size_t)(12 + it) * NP + p];
    float a1 = S[(size_t)(18 + it) * NP + p];
    float denom = fmaf(a7, S[(size_t)30 * NP + p],
                  fmaf(a5, S[(size_t)31 * NP + p],
                  fmaf(a3, S[(size_t)32 * NP + p], a1)));
    float invd = 1.0f / denom;
    float sumg = invd * fmaf(a7, S[(size_t)33 * NP + p],
                        fmaf(a5, S[(size_t)34 * NP + p],
                        fmaf(a3, S[(size_t)35 * NP + p], a1)));
    float m = invd * dt[p];
    g_scratch[(size_t)36 * NP + p] = a7 * m;
    g_scratch[(size_t)37 * NP + p] = a5 * m;
    g_scratch[(size_t)38 * NP + p] = a3 * m;
    g_scratch[(size_t)39 * NP + p] = (1.0f - sumg) * d0[p] + a1 * m;
}

// ---------------- per-iteration 48-tap gather ----------------
__device__ __constant__ const int G7DY[24] = {3,3,3,3,3,3,3, 2,2, 1,1, 0,0, -1,-1, -2,-2, -3,-3,-3,-3,-3,-3,-3};
__device__ __constant__ const int G7DX[24] = {3,2,1,0,-1,-2,-3, 3,-3, 3,-3, 3,-3, 3,-3, 3,-3, 3,2,1,0,-1,-2,-3};
__device__ __constant__ const int G5DY[16] = {2,2,2,2,2, 1,1, 0,0, -1,-1, -2,-2,-2,-2,-2};
__device__ __constant__ const int G5DX[16] = {2,1,0,-1,-2, 2,-2, 2,-2, 2,-2, 2,1,0,-1,-2};
__device__ __constant__ const int G3DY[8]  = {1,1,1, 0,0, -1,-1,-1};
__device__ __constant__ const int G3DX[8]  = {1,0,-1, 1,-1, 1,0,-1};

__global__ void iter_b(const float* __restrict__ d00, float* __restrict__ out, int it)
{
    int p = blockIdx.x * 256 + threadIdx.x;
    if (p >= NP) return;
    unsigned up = (unsigned)p;
    int b = up / (unsigned)HW_;
    unsigned r = up - (unsigned)b * HW_;
    int y = r / (unsigned)W_;
    int x = r - (unsigned)y * W_;

    const float*  S  = g_scratch;
    const __half* AF = g_aff;
    const float* A7 = S + (size_t)36 * NP;
    const float* A5 = S + (size_t)37 * NP;
    const float* A3 = S + (size_t)38 * NP;

    float acc = S[(size_t)39 * NP + p];

    #pragma unroll
    for (int t = 0; t < 24; ++t) {
        const int dy = G7DY[t], dx = G7DX[t];
        if ((unsigned)(y + dy) < (unsigned)H_ && (unsigned)(x + dx) < (unsigned)W_) {
            int q = p + dy * W_ + dx;
            acc = fmaf(__half2float(AF[(size_t)t * NP + q]), A7[q], acc);
        }
    }
    #pragma unroll
    for (int t = 0; t < 16; ++t) {
        const int dy = G5DY[t], dx = G5DX[t];
        if ((unsigned)(y + dy) < (unsigned)H_ && (unsigned)(x + dx) < (unsigned)W_) {
            int q = p + dy * W_ + dx;
            acc = fmaf(__half2float(AF[(size_t)(24 + t) * NP + q]), A5[q], acc);
        }
    }
    #pragma unroll
    for (int t = 0; t < 8; ++t) {
        const int dy = G3DY[t], dx = G3DX[t];
        if ((unsigned)(y + dy) < (unsigned)H_ && (unsigned)(x + dx) < (unsigned)W_) {
            int q = p + dy * W_ + dx;
            acc = fmaf(__half2float(AF[(size_t)(40 + t) * NP + q]), A3[q], acc);
        }
    }

    float mask = S[(size_t)(24 + it) * NP + p];
    out[p] = mask * d00[p] + (1.0f - mask) * acc;
}

// ---------------- launch ----------------
extern "C" void kernel_launch(void* const* d_in, const int* in_sizes, int n_in,
                              void* d_out, int out_size)
{
    const float* feat = (const float*)d_in[0];
    const float* d0   = (const float*)d_in[1];
    const float* d00  = (const float*)d_in[2];

    cudaFuncSetAttribute(conv_kernel, cudaFuncAttributeMaxDynamicSharedMemorySize,
                         CONV_SMEM);

    pack_weights<<<(NCH * 576 + 255) / 256, 256>>>(
        (const float*)d_in[3],  (const float*)d_in[4],  (const float*)d_in[5],
        (const float*)d_in[6],  (const float*)d_in[7],  (const float*)d_in[8],
        (const float*)d_in[9],  (const float*)d_in[10], (const float*)d_in[11],
        (const float*)d_in[12], (const float*)d_in[13], (const float*)d_in[14],
        (const float*)d_in[15], (const float*)d_in[16], (const float*)d_in[17],
        (const float*)d_in[18], (const float*)d_in[19], (const float*)d_in[20],
        (const float*)d_in[21], (const float*)d_in[22], (const float*)d_in[23],
        (const float*)d_in[24], (const float*)d_in[25], (const float*)d_in[26]);

    pack_frags<<<(36 * 10 * 32 + 255) / 256, 256>>>();

    conv_kernel<<<dim3(10, H_ / 4, B_), 512, CONV_SMEM>>>(feat, d00);

    void* sptr = nullptr;
    cudaGetSymbolAddress(&sptr, g_scratch);
    float* S = (float*)sptr;

    const int nblk = NP / 256;
    for (int it = 0; it < ITERS; ++it) {
        const float* dtcur = (it == 0) ? d0 : S + (size_t)(40 + ((it - 1) & 1)) * NP;
        float* dtnext = (it == ITERS - 1) ? (float*)d_out
                                          : S + (size_t)(40 + (it & 1)) * NP;
        iter_a<<<nblk, 256>>>(dtcur, d0, it);
        iter_b<<<nblk, 256>>>(d00, dtnext, it);
    }
}